// round 11
// baseline (speedup 1.0000x reference)
#include <cuda_runtime.h>
#include <cstdint>

// Integrator: y[b,c,n] = cumsum over time axis. 32 rows, T = 2^20.
//
// R11: register-resident single-read scan, occupancy-tuned, init-free.
//   8192 blocks x 4096 elements, 4 float4/thread, <=42 regs (6 blocks/SM).
//   Phase A: 4 streaming loads, in-register warp-span scan (exclusive prefix
//   folded into the data), one 8-wide warp-0 scan. 2 barriers total.
//   Spine: generation-tagged (gen:32|float:32). Each block reads its own
//   entry's gen r (sole writer), publishes r+1, polls preds for gen==r+1.
//   -> no init kernel needed; exactly one write per entry per launch.
//   Lookback: <=255 preds, <=8/lane, one MLP round, fixed grouping (determ.).
//   Phase B: add offset + STG.128 only.

#define THREADS 256
#define WARPS 8
#define VPT 4                          // float4 per thread
#define SEG (THREADS * VPT * 4)        // 4096
#define F4_PER_WARP 128                // 512 elems / 4
#define T_LEN 1048576
#define SEGS_PER_ROW (T_LEN / SEG)     // 256 (power of two)
#define NSEG 8192                      // 32 rows * 256

// Spine word: gen (hi 32) | float bits (lo 32). Zero-init at module load.
__device__ unsigned long long g_spine[NSEG];

__device__ __forceinline__ void spine_store(unsigned long long* p, unsigned gen, float v) {
    unsigned long long w = ((unsigned long long)gen << 32)
                         | (unsigned long long)__float_as_uint(v);
    asm volatile("st.global.relaxed.gpu.b64 [%0], %1;" :: "l"(p), "l"(w) : "memory");
}

__device__ __forceinline__ unsigned long long spine_poll(const unsigned long long* p) {
    unsigned long long v;
    asm volatile("ld.global.relaxed.gpu.b64 %0, [%1];" : "=l"(v) : "l"(p) : "memory");
    return v;
}

__global__ __launch_bounds__(THREADS, 6)
void integrator_scan_kernel(const float* __restrict__ x, float* __restrict__ y) {
    __shared__ float s_warp[WARPS];   // per-warp totals
    __shared__ float s_woff[WARPS];   // exclusive warp offsets within segment
    __shared__ float s_excl;          // exclusive prefix of this segment

    const int bid = blockIdx.x;
    const int seg_in_row = bid & (SEGS_PER_ROW - 1);
    const long long base = (long long)bid * SEG;

    const int t = threadIdx.x;
    const int lane = t & 31;
    const int warp = t >> 5;

    const float4* xv = reinterpret_cast<const float4*>(x + base);
    float4* yv = reinterpret_cast<float4*>(y + base);

    // ===== Phase A: one streaming read; warp-span scan folded into regs =====
    // Warp w owns float4 indices [w*128, (w+1)*128); sub-chunk j uses
    // j*32+lane -> sweeps 0..127 over j=0..3 (full coverage).
    float4 d[VPT];

    #pragma unroll
    for (int j = 0; j < VPT; j++)
        d[j] = __ldcs(xv + warp * F4_PER_WARP + j * 32 + lane);

    float carry = 0.0f;   // running prefix across sub-chunks (warp-internal)
    #pragma unroll
    for (int j = 0; j < VPT; j++) {
        // thread-local inclusive scan
        d[j].y += d[j].x; d[j].z += d[j].y; d[j].w += d[j].z;
        const float tot = d[j].w;
        // warp inclusive scan of totals
        float incl = tot;
        #pragma unroll
        for (int dd = 1; dd < 32; dd <<= 1) {
            float n = __shfl_up_sync(0xffffffffu, incl, dd);
            if (lane >= dd) incl += n;
        }
        // fold (carry + lane-exclusive) into the data now
        const float add = carry + (incl - tot);
        d[j].x += add; d[j].y += add; d[j].z += add; d[j].w += add;
        carry += __shfl_sync(0xffffffffu, incl, 31);
    }
    if (lane == 0) s_warp[warp] = carry;

    __syncthreads();

    if (warp == 0) {
        // scan the 8 warp totals
        const float v = (lane < WARPS) ? s_warp[lane] : 0.0f;
        float incl = v;
        #pragma unroll
        for (int dd = 1; dd < 8; dd <<= 1) {
            float n = __shfl_up_sync(0xffffffffu, incl, dd);
            if (lane >= dd) incl += n;
        }
        if (lane < WARPS) s_woff[lane] = incl - v;
        const float blocktot = __shfl_sync(0xffffffffu, incl, WARPS - 1);

        // generation handshake: sole writer of g_spine[bid] reads last gen
        unsigned target;
        if (lane == 0) {
            unsigned g_old = (unsigned)(spine_poll(&g_spine[bid]) >> 32);
            target = g_old + 1u;
            spine_store(&g_spine[bid], target, blocktot);
        }
        target = __shfl_sync(0xffffffffu, target, 0);

        // Deterministic lookback: <=255 preds, <=8/lane, MLP-batched polling,
        // fixed grouping -> bitwise deterministic.
        float excl = 0.0f;
        if (seg_in_row > 0) {
            const int rowbase = bid - seg_in_row;
            const int cnt = (seg_in_row > lane) ? ((seg_in_row - lane + 31) >> 5) : 0;
            float v8[8];
            unsigned pend = (cnt > 0) ? ((1u << cnt) - 1u) : 0u;
            while (pend) {
                unsigned long long w8[8];
                #pragma unroll
                for (int i = 0; i < 8; i++)
                    if (pend & (1u << i))
                        w8[i] = spine_poll(&g_spine[rowbase + lane + 32 * i]);
                #pragma unroll
                for (int i = 0; i < 8; i++)
                    if ((pend & (1u << i)) && (unsigned)(w8[i] >> 32) == target) {
                        v8[i] = __uint_as_float((unsigned)w8[i]);
                        pend &= ~(1u << i);
                    }
            }
            float lsum = 0.0f;
            #pragma unroll
            for (int i = 0; i < 8; i++)
                if (i < cnt) lsum += v8[i];
            #pragma unroll
            for (int dd = 16; dd; dd >>= 1)
                lsum += __shfl_xor_sync(0xffffffffu, lsum, dd);
            excl = lsum;
        }
        if (lane == 0) s_excl = excl;
    }

    __syncthreads();

    // ===== Phase B: registers -> global. No loads, no shfls, no barriers. =====
    const float off = s_excl + s_woff[warp];

    #pragma unroll
    for (int j = 0; j < VPT; j++) {
        float4 o = d[j];
        o.x += off; o.y += off; o.z += off; o.w += off;
        __stcs(yv + warp * F4_PER_WARP + j * 32 + lane, o);
    }
}

extern "C" void kernel_launch(void* const* d_in, const int* in_sizes, int n_in,
                              void* d_out, int out_size) {
    const float* x = (const float*)d_in[0];
    float* y = (float*)d_out;

    const int n = out_size;              // 33554432
    const int nseg = n / SEG;            // 8192

    integrator_scan_kernel<<<nseg, THREADS>>>(x, y);
}

// round 12
// speedup vs baseline: 1.1164x; 1.1164x over previous
#include <cuda_runtime.h>
#include <cstdint>

// Integrator: y[b,c,n] = cumsum over time axis. 32 rows, T = 2^20.
//
// R12: register-resident single-read scan; R10 grid shape at 75% occupancy.
//   4096 blocks x 8192 elements, 512 threads x 4 float4 (16 data regs).
//   Gen-tagged spine (no init kernel); own-gen read HOISTED to kernel entry
//   so its latency hides under the phase-A loads; publish immediately after
//   the block total. Lookback: <=127 preds, <=4/lane, one MLP round, fixed
//   grouping (deterministic). Phase B: add offset + STG.128 only.

#define THREADS 512
#define WARPS 16
#define VPT 4                          // float4 per thread
#define SEG (THREADS * VPT * 4)        // 8192
#define F4_PER_WARP ((SEG / 4) / WARPS) // 128
#define T_LEN 1048576
#define SEGS_PER_ROW (T_LEN / SEG)     // 128 (power of two)
#define NSEG 4096                      // 32 rows * 128

// Spine word: gen (hi 32) | float bits (lo 32). Zero at module load; each
// launch bumps every entry's gen by exactly 1 (sole-writer handshake).
__device__ unsigned long long g_spine[NSEG];

__device__ __forceinline__ void spine_store(unsigned long long* p, unsigned gen, float v) {
    unsigned long long w = ((unsigned long long)gen << 32)
                         | (unsigned long long)__float_as_uint(v);
    asm volatile("st.global.relaxed.gpu.b64 [%0], %1;" :: "l"(p), "l"(w) : "memory");
}

__device__ __forceinline__ unsigned long long spine_poll(const unsigned long long* p) {
    unsigned long long v;
    asm volatile("ld.global.relaxed.gpu.b64 %0, [%1];" : "=l"(v) : "l"(p) : "memory");
    return v;
}

__global__ __launch_bounds__(THREADS, 3)
void integrator_scan_kernel(const float* __restrict__ x, float* __restrict__ y) {
    __shared__ float s_warp[WARPS];    // per-warp totals
    __shared__ float s_woff[WARPS];    // exclusive warp offsets within segment
    __shared__ float s_excl;           // exclusive prefix of this segment
    __shared__ unsigned s_gen;         // this launch's generation for this entry

    const int bid = blockIdx.x;
    const int seg_in_row = bid & (SEGS_PER_ROW - 1);
    const long long base = (long long)bid * SEG;

    const int t = threadIdx.x;
    const int lane = t & 31;
    const int warp = t >> 5;

    // Hoisted gen read: in flight while phase A loads stream in.
    if (t == 0)
        s_gen = (unsigned)(spine_poll(&g_spine[bid]) >> 32) + 1u;

    const float4* xv = reinterpret_cast<const float4*>(x + base);
    float4* yv = reinterpret_cast<float4*>(y + base);

    // ===== Phase A: one streaming read; prefix folded into registers =====
    // Warp w owns float4 [w*128, (w+1)*128); sub-chunk j uses j*32+lane.
    float4 d[VPT];
    #pragma unroll
    for (int j = 0; j < VPT; j++)
        d[j] = __ldcs(xv + warp * F4_PER_WARP + j * 32 + lane);

    float carry = 0.0f;   // warp-internal running prefix across sub-chunks
    #pragma unroll
    for (int j = 0; j < VPT; j++) {
        d[j].y += d[j].x; d[j].z += d[j].y; d[j].w += d[j].z;
        const float tot = d[j].w;
        float incl = tot;
        #pragma unroll
        for (int dd = 1; dd < 32; dd <<= 1) {
            float n = __shfl_up_sync(0xffffffffu, incl, dd);
            if (lane >= dd) incl += n;
        }
        const float add = carry + (incl - tot);
        d[j].x += add; d[j].y += add; d[j].z += add; d[j].w += add;
        carry += __shfl_sync(0xffffffffu, incl, 31);
    }
    if (lane == 0) s_warp[warp] = carry;

    __syncthreads();

    if (warp == 0) {
        // scan the 16 warp totals
        const float v = (lane < WARPS) ? s_warp[lane] : 0.0f;
        float incl = v;
        #pragma unroll
        for (int dd = 1; dd < 16; dd <<= 1) {
            float n = __shfl_up_sync(0xffffffffu, incl, dd);
            if (lane >= dd) incl += n;
        }
        if (lane < WARPS) s_woff[lane] = incl - v;
        const float blocktot = __shfl_sync(0xffffffffu, incl, WARPS - 1);

        const unsigned target = s_gen;          // ready: read overlapped loads
        if (lane == 0) spine_store(&g_spine[bid], target, blocktot);

        // Deterministic lookback: <=127 preds, <=4/lane, MLP-batched polling,
        // fixed grouping -> bitwise deterministic.
        float excl = 0.0f;
        if (seg_in_row > 0) {
            const int rowbase = bid - seg_in_row;
            const int cnt = (seg_in_row > lane) ? ((seg_in_row - lane + 31) >> 5) : 0;
            float v4[4];
            unsigned pend = (cnt > 0) ? ((1u << cnt) - 1u) : 0u;
            while (pend) {
                unsigned long long w4[4];
                #pragma unroll
                for (int i = 0; i < 4; i++)
                    if (pend & (1u << i))
                        w4[i] = spine_poll(&g_spine[rowbase + lane + 32 * i]);
                #pragma unroll
                for (int i = 0; i < 4; i++)
                    if ((pend & (1u << i)) && (unsigned)(w4[i] >> 32) == target) {
                        v4[i] = __uint_as_float((unsigned)w4[i]);
                        pend &= ~(1u << i);
                    }
            }
            float lsum = 0.0f;
            #pragma unroll
            for (int i = 0; i < 4; i++)
                if (i < cnt) lsum += v4[i];
            #pragma unroll
            for (int dd = 16; dd; dd >>= 1)
                lsum += __shfl_xor_sync(0xffffffffu, lsum, dd);
            excl = lsum;
        }
        if (lane == 0) s_excl = excl;
    }

    __syncthreads();

    // ===== Phase B: registers -> global. No loads, no shfls, no barriers. =====
    const float off = s_excl + s_woff[warp];

    #pragma unroll
    for (int j = 0; j < VPT; j++) {
        float4 o = d[j];
        o.x += off; o.y += off; o.z += off; o.w += off;
        __stcs(yv + warp * F4_PER_WARP + j * 32 + lane, o);
    }
}

extern "C" void kernel_launch(void* const* d_in, const int* in_sizes, int n_in,
                              void* d_out, int out_size) {
    const float* x = (const float*)d_in[0];
    float* y = (float*)d_out;

    const int n = out_size;              // 33554432
    const int nseg = n / SEG;            // 4096

    integrator_scan_kernel<<<nseg, THREADS>>>(x, y);
}

// round 13
// speedup vs baseline: 1.2539x; 1.1232x over previous
#include <cuda_runtime.h>
#include <cstdint>

// Integrator: y[b,c,n] = cumsum over time axis. 32 rows, T = 2^20.
//
// R13: R10's winning shape (256 thr x 8 float4, 4096 blocks) plus:
//   - gen-tagged spine (no init kernel); own-gen read hoisted to kernel
//     entry so it rides under the 8 streaming loads.
//   - warp-span exclusive prefix folded into d[] during phase A (drops
//     lex[8] -> ~52 regs, 5 blocks/SM -> +25% in-flight load bytes).
//   Lookback: <=127 preds, <=4/lane, one MLP round, fixed grouping
//   (bitwise deterministic). Phase B: add offset + STG.128 only.

#define THREADS 256
#define WARPS 8
#define VPT 8                           // float4 per thread
#define SEG (THREADS * VPT * 4)         // 8192
#define F4_PER_WARP ((SEG / 4) / WARPS) // 256
#define T_LEN 1048576
#define SEGS_PER_ROW (T_LEN / SEG)      // 128 (power of two)
#define NSEG 4096                       // 32 rows * 128

// Spine word: gen (hi 32) | float bits (lo 32). Zero at module load; every
// launch bumps each entry's gen by exactly 1 (sole-writer handshake), so all
// entries agree on gen before each launch -> exact-match polling is safe.
__device__ unsigned long long g_spine[NSEG];

__device__ __forceinline__ void spine_store(unsigned long long* p, unsigned gen, float v) {
    unsigned long long w = ((unsigned long long)gen << 32)
                         | (unsigned long long)__float_as_uint(v);
    asm volatile("st.global.relaxed.gpu.b64 [%0], %1;" :: "l"(p), "l"(w) : "memory");
}

__device__ __forceinline__ unsigned long long spine_poll(const unsigned long long* p) {
    unsigned long long v;
    asm volatile("ld.global.relaxed.gpu.b64 %0, [%1];" : "=l"(v) : "l"(p) : "memory");
    return v;
}

__global__ __launch_bounds__(THREADS, 5)
void integrator_scan_kernel(const float* __restrict__ x, float* __restrict__ y) {
    __shared__ float s_warp[WARPS];    // per-warp totals
    __shared__ float s_woff[WARPS];    // exclusive warp offsets within segment
    __shared__ float s_excl;           // exclusive prefix of this segment
    __shared__ unsigned s_gen;         // this launch's generation

    const int bid = blockIdx.x;
    const int seg_in_row = bid & (SEGS_PER_ROW - 1);
    const long long base = (long long)bid * SEG;

    const int t = threadIdx.x;
    const int lane = t & 31;
    const int warp = t >> 5;

    // Hoisted gen read: in flight while the 8 data loads stream in.
    if (t == 0)
        s_gen = (unsigned)(spine_poll(&g_spine[bid]) >> 32) + 1u;

    const float4* xv = reinterpret_cast<const float4*>(x + base);
    float4* yv = reinterpret_cast<float4*>(y + base);

    // ===== Phase A: one streaming read; warp-span prefix folded into regs ====
    // Warp w owns float4 [w*256, (w+1)*256); sub-chunk j uses j*32+lane
    // -> sweeps 0..255 over j=0..7 (full coverage).
    float4 d[VPT];
    #pragma unroll
    for (int j = 0; j < VPT; j++)
        d[j] = __ldcs(xv + warp * F4_PER_WARP + j * 32 + lane);

    float carry = 0.0f;   // warp-internal running prefix across sub-chunks
    #pragma unroll
    for (int j = 0; j < VPT; j++) {
        d[j].y += d[j].x; d[j].z += d[j].y; d[j].w += d[j].z;
        const float tot = d[j].w;
        float incl = tot;
        #pragma unroll
        for (int dd = 1; dd < 32; dd <<= 1) {
            float n = __shfl_up_sync(0xffffffffu, incl, dd);
            if (lane >= dd) incl += n;
        }
        const float add = carry + (incl - tot);
        d[j].x += add; d[j].y += add; d[j].z += add; d[j].w += add;
        carry += __shfl_sync(0xffffffffu, incl, 31);
    }
    if (lane == 0) s_warp[warp] = carry;

    __syncthreads();

    if (warp == 0) {
        // scan the 8 warp totals
        const float v = (lane < WARPS) ? s_warp[lane] : 0.0f;
        float incl = v;
        #pragma unroll
        for (int dd = 1; dd < 8; dd <<= 1) {
            float n = __shfl_up_sync(0xffffffffu, incl, dd);
            if (lane >= dd) incl += n;
        }
        if (lane < WARPS) s_woff[lane] = incl - v;
        const float blocktot = __shfl_sync(0xffffffffu, incl, WARPS - 1);

        const unsigned target = s_gen;          // read overlapped the loads
        if (lane == 0) spine_store(&g_spine[bid], target, blocktot);

        // Deterministic lookback: <=127 preds, <=4/lane, MLP-batched polling,
        // fixed grouping -> bitwise deterministic.
        float excl = 0.0f;
        if (seg_in_row > 0) {
            const int rowbase = bid - seg_in_row;
            const int cnt = (seg_in_row > lane) ? ((seg_in_row - lane + 31) >> 5) : 0;
            float v4[4];
            unsigned pend = (cnt > 0) ? ((1u << cnt) - 1u) : 0u;
            while (pend) {
                unsigned long long w4[4];
                #pragma unroll
                for (int i = 0; i < 4; i++)
                    if (pend & (1u << i))
                        w4[i] = spine_poll(&g_spine[rowbase + lane + 32 * i]);
                #pragma unroll
                for (int i = 0; i < 4; i++)
                    if ((pend & (1u << i)) && (unsigned)(w4[i] >> 32) == target) {
                        v4[i] = __uint_as_float((unsigned)w4[i]);
                        pend &= ~(1u << i);
                    }
            }
            float lsum = 0.0f;
            #pragma unroll
            for (int i = 0; i < 4; i++)
                if (i < cnt) lsum += v4[i];
            #pragma unroll
            for (int dd = 16; dd; dd >>= 1)
                lsum += __shfl_xor_sync(0xffffffffu, lsum, dd);
            excl = lsum;
        }
        if (lane == 0) s_excl = excl;
    }

    __syncthreads();

    // ===== Phase B: registers -> global. No loads, no shfls, no barriers. ====
    const float off = s_excl + s_woff[warp];

    #pragma unroll
    for (int j = 0; j < VPT; j++) {
        float4 o = d[j];
        o.x += off; o.y += off; o.z += off; o.w += off;
        __stcs(yv + warp * F4_PER_WARP + j * 32 + lane, o);
    }
}

extern "C" void kernel_launch(void* const* d_in, const int* in_sizes, int n_in,
                              void* d_out, int out_size) {
    const float* x = (const float*)d_in[0];
    float* y = (float*)d_out;

    const int n = out_size;              // 33554432
    const int nseg = n / SEG;            // 4096

    integrator_scan_kernel<<<nseg, THREADS>>>(x, y);
}